// round 12
// baseline (speedup 1.0000x reference)
#include <cuda_runtime.h>
#include <cuda_fp16.h>
#include <cstdint>

// Problem constants (fixed shapes for this problem)
#define NNODES 8192
#define KDIM   256     // in_embedding_len
#define MOUT   128     // out_embedding_len
#define EPSV   1e-5f
#define MASK_WORDS_PER_ROW (NNODES / 32)   // 256
#define MAX_DEG 2048

// Scratch (no cudaMalloc allowed). X operands are stored DUPLICATED as (x,x)
// float2 pairs so the GEMM broadcast operand is a single LDS.64 (no pack MOVs).
__device__ __align__(16) float2  g_xd [NNODES * KDIM];   // dup of input x (16 MB)
__device__ __align__(16) float2  g_h1d[NNODES * KDIM];   // dup of h1      (16 MB)
__device__ __align__(16) float2  g_h2d[NNODES * KDIM];   // dup of h2      (16 MB)
__device__ unsigned g_mask[NNODES * MASK_WORDS_PER_ROW]; // 8 MB
__device__ __align__(16) __half2 g_embh[NNODES * MOUT / 2]; // fp16 emb for GAT (2 MB)

// ---------------- packed f32x2 helpers (Blackwell FFMA2 path) ----------------
__device__ __forceinline__ unsigned long long pk2(float lo, float hi) {
    unsigned long long r;
    asm("mov.b64 %0, {%1, %2};" : "=l"(r) : "f"(lo), "f"(hi));
    return r;
}
__device__ __forceinline__ void upk2(unsigned long long v, float& lo, float& hi) {
    asm("mov.b64 {%0, %1}, %2;" : "=f"(lo), "=f"(hi) : "l"(v));
}
__device__ __forceinline__ unsigned long long fma2(unsigned long long a,
                                                   unsigned long long b,
                                                   unsigned long long c) {
    unsigned long long d;
    asm("fma.rn.f32x2 %0, %1, %2, %3;" : "=l"(d) : "l"(a), "l"(b), "l"(c));
    return d;
}

// ---------------- cp.async helpers ----------------
__device__ __forceinline__ unsigned smem_u32(const void* p) {
    return (unsigned)__cvta_generic_to_shared(p);
}
__device__ __forceinline__ void cp16(unsigned dst, const void* src) {
    asm volatile("cp.async.ca.shared.global [%0], [%1], 16;" :: "r"(dst), "l"(src));
}
#define CP_COMMIT() asm volatile("cp.async.commit_group;")
#define CP_WAIT(N)  asm volatile("cp.async.wait_group %0;" :: "n"(N))

// ---------------- input duplication prep ----------------
// x [N,256] f32 -> g_xd [N,256] (x,x) float2. One float4 in, two float4 out.
__global__ void dup_x_kernel(const float* __restrict__ x) {
    int i = blockIdx.x * blockDim.x + threadIdx.x;    // N*256/4 = 524288
    float4 v = reinterpret_cast<const float4*>(x)[i];
    float4* o = reinterpret_cast<float4*>(&g_xd[i * 4]);
    o[0] = make_float4(v.x, v.x, v.y, v.y);
    o[1] = make_float4(v.z, v.z, v.w, v.w);
}

// ====== fused GEMM + bias + LayerNorm (+tanh), dup-X operand ======
// Xd: [N,256] duplicated float2. W: [256,M], M in {256,128}.
// 256 threads = 8 warps; warp w owns rows w*4..w*4+3; lane tx owns cols
// {tx*4..+3} (+ {128+tx*4..+3} when M=256) -> LN is pure warp shfl.
// Inner loop per kk per thread: 4 broadcast LDS.64 (aa) + CP2/2 LDS.128 (W)
// + 4*CP2 FFMA2  ->  ~70% FFMA2 issue mix (R11 was ~50% due to pack MOVs).
// OUTMODE: 0 = write dup float2 (next GEMM), 1 = write fp32 out + fp16 copy.
template <int M, bool DO_TANH, int OUTMODE>
__device__ __forceinline__
void gemm_ln_body(const float2* __restrict__ Xd, const float* __restrict__ W,
                  const float* __restrict__ bias, const float* __restrict__ gam,
                  const float* __restrict__ bet, void* __restrict__ outp)
{
    constexpr int K   = 256;
    constexpr int BM  = 32;
    constexpr int BK  = 16;
    constexpr int CP2 = M / 64;          // packed col-pairs per lane: 4 or 2
    constexpr int WST = M + 4;

    __shared__ __align__(16) float2 Xs[2][BM][BK];      // dup pairs, 8 KB
    __shared__ __align__(16) float  Ws[2][BK][WST];     // 33.3 / 16.9 KB

    const int t    = threadIdx.x;        // 0..255
    const int tx   = t & 31;
    const int w    = t >> 5;             // 0..7
    const int rw   = w * 4;
    const int row0 = blockIdx.x * BM;

    auto load_chunk = [&](int c, int b) {
        const int k0 = c * BK;
        // X dup tile 32 rows x 16 pairs = 256 x 16B, 1 per thread
        {
            int r   = t >> 3;
            int seg = t & 7;             // 2 float2 per 16B
            cp16(smem_u32(&Xs[b][r][seg * 2]),
                 Xd + (row0 + r) * K + k0 + seg * 2);
        }
        // W tile 16 x M
        const float* wsrc = W + k0 * M;
        constexpr int WF4 = (BK * M / 4) / 256;   // 4 (M=256) / 2 (M=128)
#pragma unroll
        for (int i = 0; i < WF4; i++) {
            int idx = t + i * 256;
            int kk  = idx / (M / 4);
            int c4  = idx % (M / 4);
            cp16(smem_u32(&Ws[b][kk][c4 * 4]), wsrc + idx * 4);
        }
    };

    unsigned long long acc[4][CP2];
#pragma unroll
    for (int r = 0; r < 4; r++)
#pragma unroll
        for (int j = 0; j < CP2; j++) acc[r][j] = 0ull;

    load_chunk(0, 0);
    CP_COMMIT();

    int buf = 0;
#pragma unroll 1
    for (int c = 0; c < K / BK; c++) {
        if (c + 1 < K / BK) {
            load_chunk(c + 1, buf ^ 1);
            CP_COMMIT();
            CP_WAIT(1);
        } else {
            CP_WAIT(0);
        }
        __syncthreads();

#pragma unroll
        for (int kk = 0; kk < BK; kk++) {
            // broadcast duplicated X: one LDS.64 per row, no pack MOVs
            unsigned long long aa[4];
#pragma unroll
            for (int r = 0; r < 4; r++)
                aa[r] = *reinterpret_cast<const unsigned long long*>(&Xs[buf][rw + r][kk]);

            unsigned long long bp[CP2];
            {
                float4 w0 = *reinterpret_cast<const float4*>(&Ws[buf][kk][tx * 4]);
                bp[0] = pk2(w0.x, w0.y);
                bp[1] = pk2(w0.z, w0.w);
                if (CP2 == 4) {
                    float4 w1 = *reinterpret_cast<const float4*>(&Ws[buf][kk][128 + tx * 4]);
                    bp[2] = pk2(w1.x, w1.y);
                    bp[3] = pk2(w1.z, w1.w);
                }
            }
#pragma unroll
            for (int r = 0; r < 4; r++)
#pragma unroll
                for (int j = 0; j < CP2; j++)
                    acc[r][j] = fma2(aa[r], bp[j], acc[r][j]);
        }
        __syncthreads();
        buf ^= 1;
    }

    // ---- epilogue: bias + LayerNorm (+tanh), full warp-shfl per row ----
    const int cb0 = tx * 4;
    const int cb1 = 128 + tx * 4;        // only used when M=256
    float bs[8], gs[8], bes[8];
#pragma unroll
    for (int c = 0; c < 4; c++) {
        bs[c] = bias[cb0 + c]; gs[c] = gam[cb0 + c]; bes[c] = bet[cb0 + c];
    }
    if (CP2 == 4) {
#pragma unroll
        for (int c = 0; c < 4; c++) {
            bs[4 + c] = bias[cb1 + c]; gs[4 + c] = gam[cb1 + c]; bes[4 + c] = bet[cb1 + c];
        }
    }

#pragma unroll
    for (int r = 0; r < 4; r++) {
        float v[8];
#pragma unroll
        for (int j = 0; j < CP2; j++) upk2(acc[r][j], v[2 * j], v[2 * j + 1]);
        float s = 0.f, ss = 0.f;
#pragma unroll
        for (int c = 0; c < 2 * CP2; c++) {
            v[c] += bs[c];
            s  += v[c];
            ss += v[c] * v[c];
        }
#pragma unroll
        for (int o = 16; o > 0; o >>= 1) {
            s  += __shfl_xor_sync(0xffffffffu, s, o);
            ss += __shfl_xor_sync(0xffffffffu, ss, o);
        }
        const float mu   = s * (1.0f / M);
        const float var  = ss * (1.0f / M) - mu * mu;
        const float rstd = rsqrtf(var + EPSV);
        const int   row  = row0 + rw + r;

        float ov[8];
#pragma unroll
        for (int c = 0; c < 2 * CP2; c++) {
            float o = (v[c] - mu) * rstd * gs[c] + bes[c];
            if (DO_TANH) o = tanhf(o);
            ov[c] = o;
        }

        if (OUTMODE == 0) {
            // duplicated float2 output for the next GEMM
            float2* od = reinterpret_cast<float2*>(outp);
            float4* o0 = reinterpret_cast<float4*>(&od[row * M + cb0]);
            o0[0] = make_float4(ov[0], ov[0], ov[1], ov[1]);
            o0[1] = make_float4(ov[2], ov[2], ov[3], ov[3]);
            if (CP2 == 4) {
                float4* o1 = reinterpret_cast<float4*>(&od[row * M + cb1]);
                o1[0] = make_float4(ov[4], ov[4], ov[5], ov[5]);
                o1[1] = make_float4(ov[6], ov[6], ov[7], ov[7]);
            }
        } else {
            // fp32 output (emb) + fp16 copy for the GAT fast path (M=128)
            float* of = reinterpret_cast<float*>(outp);
            *reinterpret_cast<float4*>(&of[row * M + cb0]) =
                make_float4(ov[0], ov[1], ov[2], ov[3]);
            __half2* hp = &g_embh[row * (MOUT / 2) + tx * 2];
            hp[0] = __floats2half2_rn(ov[0], ov[1]);
            hp[1] = __floats2half2_rn(ov[2], ov[3]);
        }
    }
}

// Wrappers referencing device globals directly
__global__ __launch_bounds__(256, 2)
void gemm_ln_l1(const float* __restrict__ W, const float* __restrict__ b,
                const float* __restrict__ g, const float* __restrict__ be)
{
    gemm_ln_body<256, true, 0>(g_xd, W, b, g, be, g_h1d);
}
__global__ __launch_bounds__(256, 2)
void gemm_ln_l2(const float* __restrict__ W, const float* __restrict__ b,
                const float* __restrict__ g, const float* __restrict__ be)
{
    gemm_ln_body<256, true, 0>(g_h1d, W, b, g, be, g_h2d);
}
__global__ __launch_bounds__(256, 2)
void gemm_ln_l3(const float* __restrict__ W, const float* __restrict__ b,
                const float* __restrict__ g, const float* __restrict__ be,
                float* __restrict__ emb)
{
    gemm_ln_body<128, false, 1>(g_h2d, W, b, g, be, emb);
}

// ---------------- adjacency bitmask ----------------
__global__ void zero_mask_kernel() {
    int i = blockIdx.x * blockDim.x + threadIdx.x;   // 2048*256 = 524288 uint4
    reinterpret_cast<uint4*>(g_mask)[i] = make_uint4(0u, 0u, 0u, 0u);
}

__global__ void set_edges_kernel(const int* __restrict__ ei, int E) {
    int e = blockIdx.x * blockDim.x + threadIdx.x;
    if (e >= E) return;
    int s = ei[e] - 1;         // 1-indexed input
    int d = ei[E + e] - 1;
    atomicOr(&g_mask[(unsigned)(s * NNODES + d) >> 5], 1u << (d & 31));
    atomicOr(&g_mask[(unsigned)(d * NNODES + s) >> 5], 1u << (s & 31));
}

// ---------------- sparse GAT row kernel (single-pass, fp16 neighbors) ----------------
__global__ __launch_bounds__(128)
void gat_row_kernel(const float* __restrict__ emb, float* __restrict__ xgat)
{
    const int i    = blockIdx.x;
    const int t    = threadIdx.x;
    const int lane = t & 31;
    const int wid  = t >> 5;

    __shared__ __align__(16) float ei_s[MOUT];
    __shared__ __align__(16) float wout[4][MOUT];
    __shared__ __align__(16) int   nbr[MAX_DEG];
    __shared__ float wden[4];
    __shared__ int   cnt;

    ei_s[t] = emb[i * MOUT + t];       // center row stays fp32
    if (t == 0) cnt = 0;
    __syncthreads();

    // 1) compact the set bits of mask row i
    const unsigned* row = &g_mask[i * MASK_WORDS_PER_ROW];
#pragma unroll
    for (int w = t; w < MASK_WORDS_PER_ROW; w += 128) {
        unsigned m = row[w];
        while (m) {
            int b = __ffs(m) - 1;
            m &= m - 1;
            int p = atomicAdd(&cnt, 1);
            if (p < MAX_DEG) nbr[p] = w * 32 + b;
        }
    }
    __syncthreads();
    const int deg = cnt < MAX_DEG ? cnt : MAX_DEG;

    // 2) fused score + aggregate (warp per neighbor), half2 loads
    const float4 ei4 = *reinterpret_cast<const float4*>(&ei_s[lane * 4]);
    float4 oac = make_float4(0.f, 0.f, 0.f, 0.f);
    float  dsum = 0.f;

    for (int n = wid; n < deg; n += 4) {
        const __half2* hp = &g_embh[nbr[n] * (MOUT / 2) + lane * 2];
        const float2 f0 = __half22float2(hp[0]);
        const float2 f1 = __half22float2(hp[1]);
        float d = f0.x * ei4.x + f0.y * ei4.y + f1.x * ei4.z + f1.y * ei4.w;
#pragma unroll
        for (int o = 16; o > 0; o >>= 1) d += __shfl_xor_sync(0xffffffffu, d, o);
        const float s = expf(d);
        dsum  += s;
        oac.x += s * f0.x;
        oac.y += s * f0.y;
        oac.z += s * f1.x;
        oac.w += s * f1.y;
    }
    *reinterpret_cast<float4*>(&wout[wid][lane * 4]) = oac;
    if (lane == 0) wden[wid] = dsum;
    __syncthreads();

    // 3) cross-warp combine + normalize
    const float den  = wden[0] + wden[1] + wden[2] + wden[3];
    const float invd = den > 0.f ? 1.0f / den : 0.0f;
    const float tot  = wout[0][t] + wout[1][t] + wout[2][t] + wout[3][t];
    xgat[i * MOUT + t] = tot * invd;
}

// ---------------- launch ----------------
extern "C" void kernel_launch(void* const* d_in, const int* in_sizes, int n_in,
                              void* d_out, int out_size)
{
    const float* x   = (const float*)d_in[0];
    const int*   ei  = (const int*)d_in[1];
    const float* w1  = (const float*)d_in[2];
    const float* b1  = (const float*)d_in[3];
    const float* g1  = (const float*)d_in[4];
    const float* be1 = (const float*)d_in[5];
    const float* w2  = (const float*)d_in[6];
    const float* b2  = (const float*)d_in[7];
    const float* g2  = (const float*)d_in[8];
    const float* be2 = (const float*)d_in[9];
    const float* w3  = (const float*)d_in[10];
    const float* b3  = (const float*)d_in[11];
    const float* g3  = (const float*)d_in[12];
    const float* be3 = (const float*)d_in[13];

    float* out  = (float*)d_out;
    float* emb  = out;                     // [N, 128]
    float* xgat = out + NNODES * MOUT;     // [N, 128]

    const int E = in_sizes[1] / 2;

    // adjacency bitmask + input duplication (independent prep)
    zero_mask_kernel<<<2048, 256>>>();
    set_edges_kernel<<<(E + 255) / 256, 256>>>(ei, E);
    dup_x_kernel<<<2048, 256>>>(x);

    // encoder (dup-X operand chain)
    gemm_ln_l1<<<NNODES / 32, 256>>>(w1, b1, g1, be1);
    gemm_ln_l2<<<NNODES / 32, 256>>>(w2, b2, g2, be2);
    gemm_ln_l3<<<NNODES / 32, 256>>>(w3, b3, g3, be3, emb);

    // sparse GAT (fused single pass, fp16 neighbor reads)
    gat_row_kernel<<<NNODES, 128>>>(emb, xgat);
}

// round 13
// speedup vs baseline: 1.0409x; 1.0409x over previous
#include <cuda_runtime.h>
#include <cuda_fp16.h>
#include <cstdint>

// Problem constants (fixed shapes for this problem)
#define NNODES 8192
#define KDIM   256     // in_embedding_len
#define MOUT   128     // out_embedding_len
#define EPSV   1e-5f
#define MASK_WORDS_PER_ROW (NNODES / 32)   // 256
#define MAX_DEG 2048

// Scratch (no cudaMalloc allowed)
__device__ float    g_h1[NNODES * KDIM];                    // 8 MB
__device__ float    g_h2[NNODES * KDIM];                    // 8 MB
__device__ unsigned g_mask[NNODES * MASK_WORDS_PER_ROW];    // 8 MB
__device__ __align__(16) __half2 g_embh[NNODES * MOUT / 2]; // fp16 emb for GAT (2 MB)
// K-paired weights: Wp[kp*M + c] = (W[2kp][c], W[2kp+1][c])
__device__ __align__(16) float2 g_w1p[(KDIM / 2) * KDIM];   // 256 KB
__device__ __align__(16) float2 g_w2p[(KDIM / 2) * KDIM];   // 256 KB
__device__ __align__(16) float2 g_w3p[(KDIM / 2) * MOUT];   // 128 KB

// ---------------- packed f32x2 helpers (Blackwell FFMA2 path) ----------------
__device__ __forceinline__ void upk2(unsigned long long v, float& lo, float& hi) {
    asm("mov.b64 {%0, %1}, %2;" : "=f"(lo), "=f"(hi) : "l"(v));
}
__device__ __forceinline__ unsigned long long fma2(unsigned long long a,
                                                   unsigned long long b,
                                                   unsigned long long c) {
    unsigned long long d;
    asm("fma.rn.f32x2 %0, %1, %2, %3;" : "=l"(d) : "l"(a), "l"(b), "l"(c));
    return d;
}

// ---------------- cp.async helpers ----------------
__device__ __forceinline__ unsigned smem_u32(const void* p) {
    return (unsigned)__cvta_generic_to_shared(p);
}
__device__ __forceinline__ void cp16(unsigned dst, const void* src) {
    asm volatile("cp.async.ca.shared.global [%0], [%1], 16;" :: "r"(dst), "l"(src));
}
#define CP_COMMIT() asm volatile("cp.async.commit_group;")
#define CP_WAIT(N)  asm volatile("cp.async.wait_group %0;" :: "n"(N))

// ---------------- W pre-pairing ----------------
// Wp[kp*M + c] = (W[2kp][c], W[2kp+1][c]); kp in [0,128), c in [0,M).
__global__ void pair_w_kernel(const float* __restrict__ W, float2* __restrict__ Wp, int M) {
    int i = blockIdx.x * blockDim.x + threadIdx.x;
    if (i >= 128 * M) return;
    int kp = i / M, c = i - kp * M;
    Wp[i] = make_float2(W[(2 * kp) * M + c], W[(2 * kp + 1) * M + c]);
}

// ====== M=256 GEMM + bias + LN + tanh, K-paired FFMA2 ======
// 256 threads = 8 warps. Warp w: rows (w&3)*8..+7, column half (w>>2)*128.
// Lane tx: 4 cols. acc[r][c] packs (even-k, odd-k) partial sums; folded in
// the epilogue. Per warp-kp: 8 broadcast LDS.64 (aa, natural k-pairs) +
// 2 LDS.128 (paired W, register quads alias as b64 — ZERO pack MOVs) +
// 32 FFMA2 -> ~70% FFMA2 issue mix (R11 measured ~52%).
template <bool DO_TANH>
__device__ __forceinline__
void gemm_ln_body256(const float* __restrict__ X, const float2* __restrict__ Wp,
                     const float* __restrict__ bias, const float* __restrict__ gam,
                     const float* __restrict__ bet, float* __restrict__ out)
{
    constexpr int M = 256, K = 256, BM = 32, BK = 16, BKP = BK / 2;

    __shared__ __align__(16) float  Xs[2][BM][BK + 4];      // k-contiguous rows
    __shared__ __align__(16) float2 Wsp[2][BKP][M + 2];     // paired W tile
    __shared__ float sred_s [2][BM];
    __shared__ float sred_ss[2][BM];

    const int t    = threadIdx.x;       // 0..255
    const int tx   = t & 31;
    const int w    = t >> 5;            // 0..7
    const int rw   = (w & 3) * 8;
    const int ch   = w >> 2;            // column half
    const int cb   = ch * 128 + tx * 4; // first col (of 4) for this lane
    const int row0 = blockIdx.x * BM;

    auto load_chunk = [&](int c, int b) {
        const int k0  = c * BK;
        const int k0p = c * BKP;
        if (t < 128) {                  // X tile 32x16 = 128 x 16B
            int r  = t >> 2;
            int c4 = t & 3;
            cp16(smem_u32(&Xs[b][r][c4 * 4]), X + (row0 + r) * K + k0 + c4 * 4);
        }
        // Wp chunk: 8 rows x 256 float2 = 1024 x 16B, contiguous in gmem
#pragma unroll
        for (int i = 0; i < 4; i++) {
            int u  = t + i * 256;
            int kp = u >> 7;            // 128 16B-units per row
            int c2 = u & 127;
            cp16(smem_u32(&Wsp[b][kp][c2 * 2]), Wp + k0p * 256 + u * 2);
        }
    };

    unsigned long long acc[8][4];
#pragma unroll
    for (int r = 0; r < 8; r++)
#pragma unroll
        for (int j = 0; j < 4; j++) acc[r][j] = 0ull;

    load_chunk(0, 0);
    CP_COMMIT();

    int buf = 0;
#pragma unroll 1
    for (int c = 0; c < K / BK; c++) {
        if (c + 1 < K / BK) {
            load_chunk(c + 1, buf ^ 1);
            CP_COMMIT();
            CP_WAIT(1);
        } else {
            CP_WAIT(0);
        }
        __syncthreads();

#pragma unroll
        for (int kp = 0; kp < BKP; kp++) {
            ulonglong2 u0 = *reinterpret_cast<const ulonglong2*>(&Wsp[buf][kp][cb]);
            ulonglong2 u1 = *reinterpret_cast<const ulonglong2*>(&Wsp[buf][kp][cb + 2]);
#pragma unroll
            for (int r = 0; r < 8; r++) {
                unsigned long long aa =
                    *reinterpret_cast<const unsigned long long*>(&Xs[buf][rw + r][kp * 2]);
                acc[r][0] = fma2(aa, u0.x, acc[r][0]);
                acc[r][1] = fma2(aa, u0.y, acc[r][1]);
                acc[r][2] = fma2(aa, u1.x, acc[r][2]);
                acc[r][3] = fma2(aa, u1.y, acc[r][3]);
            }
        }
        __syncthreads();
        buf ^= 1;
    }

    // ---- epilogue: fold k-pairs, bias, LN partials, cross-half combine ----
    float bs[4]  = {bias[cb], bias[cb + 1], bias[cb + 2], bias[cb + 3]};
    float gs[4]  = {gam[cb],  gam[cb + 1],  gam[cb + 2],  gam[cb + 3]};
    float bes[4] = {bet[cb],  bet[cb + 1],  bet[cb + 2],  bet[cb + 3]};

    float v[8][4];
#pragma unroll
    for (int r = 0; r < 8; r++) {
        float s = 0.f, ss = 0.f;
#pragma unroll
        for (int j = 0; j < 4; j++) {
            float e, o;
            upk2(acc[r][j], e, o);
            float val = e + o + bs[j];
            v[r][j] = val;
            s  += val;
            ss += val * val;
        }
#pragma unroll
        for (int o = 16; o > 0; o >>= 1) {
            s  += __shfl_xor_sync(0xffffffffu, s, o);
            ss += __shfl_xor_sync(0xffffffffu, ss, o);
        }
        if (tx == 0) {
            sred_s [ch][rw + r] = s;
            sred_ss[ch][rw + r] = ss;
        }
    }
    __syncthreads();

#pragma unroll
    for (int r = 0; r < 8; r++) {
        const float s    = sred_s [0][rw + r] + sred_s [1][rw + r];
        const float ss   = sred_ss[0][rw + r] + sred_ss[1][rw + r];
        const float mu   = s * (1.0f / M);
        const float var  = ss * (1.0f / M) - mu * mu;
        const float rstd = rsqrtf(var + EPSV);
        const int   row  = row0 + rw + r;

        float ov[4];
#pragma unroll
        for (int c2 = 0; c2 < 4; c2++) {
            float o = (v[r][c2] - mu) * rstd * gs[c2] + bes[c2];
            if (DO_TANH) o = tanhf(o);
            ov[c2] = o;
        }
        *reinterpret_cast<float4*>(&out[row * M + cb]) =
            make_float4(ov[0], ov[1], ov[2], ov[3]);
    }
}

// ====== M=128 GEMM + bias + LN (no tanh), K-paired FFMA2, EMIT fp16 ======
// 128 threads = 4 warps; warp w: rows w*8..+7, lane tx: 4 cols (full M=128).
__device__ __forceinline__
void gemm_ln_body128(const float* __restrict__ X, const float2* __restrict__ Wp,
                     const float* __restrict__ bias, const float* __restrict__ gam,
                     const float* __restrict__ bet, float* __restrict__ out)
{
    constexpr int M = 128, K = 256, BM = 32, BK = 16, BKP = BK / 2;

    __shared__ __align__(16) float  Xs[2][BM][BK + 4];
    __shared__ __align__(16) float2 Wsp[2][BKP][M + 2];

    const int t    = threadIdx.x;       // 0..127
    const int tx   = t & 31;
    const int w    = t >> 5;            // 0..3
    const int rw   = w * 8;
    const int cb   = tx * 4;
    const int row0 = blockIdx.x * BM;

    auto load_chunk = [&](int c, int b) {
        const int k0  = c * BK;
        const int k0p = c * BKP;
        {
            int r  = t >> 2;
            int c4 = t & 3;
            cp16(smem_u32(&Xs[b][r][c4 * 4]), X + (row0 + r) * K + k0 + c4 * 4);
        }
        // Wp chunk: 8 rows x 128 float2 = 512 x 16B
#pragma unroll
        for (int i = 0; i < 4; i++) {
            int u  = t + i * 128;
            int kp = u >> 6;            // 64 16B-units per row
            int c2 = u & 63;
            cp16(smem_u32(&Wsp[b][kp][c2 * 2]), Wp + k0p * 128 + u * 2);
        }
    };

    unsigned long long acc[8][4];
#pragma unroll
    for (int r = 0; r < 8; r++)
#pragma unroll
        for (int j = 0; j < 4; j++) acc[r][j] = 0ull;

    load_chunk(0, 0);
    CP_COMMIT();

    int buf = 0;
#pragma unroll 1
    for (int c = 0; c < K / BK; c++) {
        if (c + 1 < K / BK) {
            load_chunk(c + 1, buf ^ 1);
            CP_COMMIT();
            CP_WAIT(1);
        } else {
            CP_WAIT(0);
        }
        __syncthreads();

#pragma unroll
        for (int kp = 0; kp < BKP; kp++) {
            ulonglong2 u0 = *reinterpret_cast<const ulonglong2*>(&Wsp[buf][kp][cb]);
            ulonglong2 u1 = *reinterpret_cast<const ulonglong2*>(&Wsp[buf][kp][cb + 2]);
#pragma unroll
            for (int r = 0; r < 8; r++) {
                unsigned long long aa =
                    *reinterpret_cast<const unsigned long long*>(&Xs[buf][rw + r][kp * 2]);
                acc[r][0] = fma2(aa, u0.x, acc[r][0]);
                acc[r][1] = fma2(aa, u0.y, acc[r][1]);
                acc[r][2] = fma2(aa, u1.x, acc[r][2]);
                acc[r][3] = fma2(aa, u1.y, acc[r][3]);
            }
        }
        __syncthreads();
        buf ^= 1;
    }

    // ---- epilogue: fold k-pairs, bias, LN (intra-warp), fp32 + fp16 out ----
    float bs[4]  = {bias[cb], bias[cb + 1], bias[cb + 2], bias[cb + 3]};
    float gs[4]  = {gam[cb],  gam[cb + 1],  gam[cb + 2],  gam[cb + 3]};
    float bes[4] = {bet[cb],  bet[cb + 1],  bet[cb + 2],  bet[cb + 3]};

#pragma unroll
    for (int r = 0; r < 8; r++) {
        float v[4];
        float s = 0.f, ss = 0.f;
#pragma unroll
        for (int j = 0; j < 4; j++) {
            float e, o;
            upk2(acc[r][j], e, o);
            v[j] = e + o + bs[j];
            s  += v[j];
            ss += v[j] * v[j];
        }
#pragma unroll
        for (int o = 16; o > 0; o >>= 1) {
            s  += __shfl_xor_sync(0xffffffffu, s, o);
            ss += __shfl_xor_sync(0xffffffffu, ss, o);
        }
        const float mu   = s * (1.0f / M);
        const float var  = ss * (1.0f / M) - mu * mu;
        const float rstd = rsqrtf(var + EPSV);
        const int   row  = row0 + rw + r;

        float ov[4];
#pragma unroll
        for (int c2 = 0; c2 < 4; c2++)
            ov[c2] = (v[c2] - mu) * rstd * gs[c2] + bes[c2];

        *reinterpret_cast<float4*>(&out[row * M + cb]) =
            make_float4(ov[0], ov[1], ov[2], ov[3]);

        __half2* hp = &g_embh[row * (MOUT / 2) + tx * 2];
        hp[0] = __floats2half2_rn(ov[0], ov[1]);
        hp[1] = __floats2half2_rn(ov[2], ov[3]);
    }
}

// Wrappers referencing device globals directly
__global__ __launch_bounds__(256, 2)
void gemm_ln_l1(const float* __restrict__ X, const float* __restrict__ b,
                const float* __restrict__ g, const float* __restrict__ be)
{
    gemm_ln_body256<true>(X, g_w1p, b, g, be, g_h1);
}
__global__ __launch_bounds__(256, 2)
void gemm_ln_l2(const float* __restrict__ b, const float* __restrict__ g,
                const float* __restrict__ be)
{
    gemm_ln_body256<true>(g_h1, g_w2p, b, g, be, g_h2);
}
__global__ __launch_bounds__(128, 2)
void gemm_ln_l3(const float* __restrict__ b, const float* __restrict__ g,
                const float* __restrict__ be, float* __restrict__ emb)
{
    gemm_ln_body128(g_h2, g_w3p, b, g, be, emb);
}

// Pairing wrappers write the device globals directly (no symbol lookup)
__global__ void pair_w1_kernel(const float* __restrict__ W) {
    int i = blockIdx.x * blockDim.x + threadIdx.x;
    if (i >= 128 * 256) return;
    int kp = i >> 8, c = i & 255;
    g_w1p[i] = make_float2(W[(2 * kp) * 256 + c], W[(2 * kp + 1) * 256 + c]);
}
__global__ void pair_w2_kernel(const float* __restrict__ W) {
    int i = blockIdx.x * blockDim.x + threadIdx.x;
    if (i >= 128 * 256) return;
    int kp = i >> 8, c = i & 255;
    g_w2p[i] = make_float2(W[(2 * kp) * 256 + c], W[(2 * kp + 1) * 256 + c]);
}
__global__ void pair_w3_kernel(const float* __restrict__ W) {
    int i = blockIdx.x * blockDim.x + threadIdx.x;
    if (i >= 128 * 128) return;
    int kp = i >> 7, c = i & 127;
    g_w3p[i] = make_float2(W[(2 * kp) * 128 + c], W[(2 * kp + 1) * 128 + c]);
}

// ---------------- adjacency bitmask ----------------
__global__ void zero_mask_kernel() {
    int i = blockIdx.x * blockDim.x + threadIdx.x;   // 2048*256 = 524288 uint4
    reinterpret_cast<uint4*>(g_mask)[i] = make_uint4(0u, 0u, 0u, 0u);
}

__global__ void set_edges_kernel(const int* __restrict__ ei, int E) {
    int e = blockIdx.x * blockDim.x + threadIdx.x;
    if (e >= E) return;
    int s = ei[e] - 1;         // 1-indexed input
    int d = ei[E + e] - 1;
    atomicOr(&g_mask[(unsigned)(s * NNODES + d) >> 5], 1u << (d & 31));
    atomicOr(&g_mask[(unsigned)(d * NNODES + s) >> 5], 1u << (s & 31));
}

// ---------------- sparse GAT row kernel (single-pass, fp16 neighbors) ----------------
__global__ __launch_bounds__(128)
void gat_row_kernel(const float* __restrict__ emb, float* __restrict__ xgat)
{
    const int i    = blockIdx.x;
    const int t    = threadIdx.x;
    const int lane = t & 31;
    const int wid  = t >> 5;

    __shared__ __align__(16) float ei_s[MOUT];
    __shared__ __align__(16) float wout[4][MOUT];
    __shared__ __align__(16) int   nbr[MAX_DEG];
    __shared__ float wden[4];
    __shared__ int   cnt;

    ei_s[t] = emb[i * MOUT + t];       // center row stays fp32
    if (t == 0) cnt = 0;
    __syncthreads();

    // 1) compact the set bits of mask row i
    const unsigned* row = &g_mask[i * MASK_WORDS_PER_ROW];
#pragma unroll
    for (int w = t; w < MASK_WORDS_PER_ROW; w += 128) {
        unsigned m = row[w];
        while (m) {
            int b = __ffs(m) - 1;
            m &= m - 1;
            int p = atomicAdd(&cnt, 1);
            if (p < MAX_DEG) nbr[p] = w * 32 + b;
        }
    }
    __syncthreads();
    const int deg = cnt < MAX_DEG ? cnt : MAX_DEG;

    // 2) fused score + aggregate (warp per neighbor), half2 loads
    const float4 ei4 = *reinterpret_cast<const float4*>(&ei_s[lane * 4]);
    float4 oac = make_float4(0.f, 0.f, 0.f, 0.f);
    float  dsum = 0.f;

    for (int n = wid; n < deg; n += 4) {
        const __half2* hp = &g_embh[nbr[n] * (MOUT / 2) + lane * 2];
        const float2 f0 = __half22float2(hp[0]);
        const float2 f1 = __half22float2(hp[1]);
        float d = f0.x * ei4.x + f0.y * ei4.y + f1.x * ei4.z + f1.y * ei4.w;
#pragma unroll
        for (int o = 16; o > 0; o >>= 1) d += __shfl_xor_sync(0xffffffffu, d, o);
        const float s = expf(d);
        dsum  += s;
        oac.x += s * f0.x;
        oac.y += s * f0.y;
        oac.z += s * f1.x;
        oac.w += s * f1.y;
    }
    *reinterpret_cast<float4*>(&wout[wid][lane * 4]) = oac;
    if (lane == 0) wden[wid] = dsum;
    __syncthreads();

    // 3) cross-warp combine + normalize
    const float den  = wden[0] + wden[1] + wden[2] + wden[3];
    const float invd = den > 0.f ? 1.0f / den : 0.0f;
    const float tot  = wout[0][t] + wout[1][t] + wout[2][t] + wout[3][t];
    xgat[i * MOUT + t] = tot * invd;
}

// ---------------- launch ----------------
extern "C" void kernel_launch(void* const* d_in, const int* in_sizes, int n_in,
                              void* d_out, int out_size)
{
    const float* x   = (const float*)d_in[0];
    const int*   ei  = (const int*)d_in[1];
    const float* w1  = (const float*)d_in[2];
    const float* b1  = (const float*)d_in[3];
    const float* g1  = (const float*)d_in[4];
    const float* be1 = (const float*)d_in[5];
    const float* w2  = (const float*)d_in[6];
    const float* b2  = (const float*)d_in[7];
    const float* g2  = (const float*)d_in[8];
    const float* be2 = (const float*)d_in[9];
    const float* w3  = (const float*)d_in[10];
    const float* b3  = (const float*)d_in[11];
    const float* g3  = (const float*)d_in[12];
    const float* be3 = (const float*)d_in[13];

    float* out  = (float*)d_out;
    float* emb  = out;                     // [N, 128]
    float* xgat = out + NNODES * MOUT;     // [N, 128]

    const int E = in_sizes[1] / 2;

    // prep: adjacency bitmask + K-paired weights
    zero_mask_kernel<<<2048, 256>>>();
    set_edges_kernel<<<(E + 255) / 256, 256>>>(ei, E);
    pair_w1_kernel<<<128, 256>>>(w1);
    pair_w2_kernel<<<128, 256>>>(w2);
    pair_w3_kernel<<<64, 256>>>(w3);

    // encoder
    gemm_ln_l1<<<NNODES / 32, 256>>>(x, b1, g1, be1);
    gemm_ln_l2<<<NNODES / 32, 256>>>(b2, g2, be2);
    gemm_ln_l3<<<NNODES / 32, 128>>>(b3, g3, be3, emb);

    // sparse GAT (fused single pass, fp16 neighbor reads)
    gat_row_kernel<<<NNODES, 128>>>(emb, xgat);
}

// round 14
// speedup vs baseline: 1.5505x; 1.4896x over previous
#include <cuda_runtime.h>
#include <cuda_fp16.h>
#include <cstdint>

#define NNODES 8192
#define KDIM   256
#define MOUT   128
#define EPSV   1e-5f
#define MASK_WORDS_PER_ROW (NNODES / 32)   // 256
#define MAX_DEG 2048

// ---------------- scratch (no cudaMalloc allowed) ----------------
__device__ __align__(16) __half g_xh [NNODES * KDIM];   // hi/lo fp16 splits
__device__ __align__(16) __half g_xl [NNODES * KDIM];
__device__ __align__(16) __half g_h1h[NNODES * KDIM];
__device__ __align__(16) __half g_h1l[NNODES * KDIM];
__device__ __align__(16) __half g_h2h[NNODES * KDIM];
__device__ __align__(16) __half g_h2l[NNODES * KDIM];
__device__ __align__(16) __half g_w1h[KDIM * KDIM];
__device__ __align__(16) __half g_w1l[KDIM * KDIM];
__device__ __align__(16) __half g_w2h[KDIM * KDIM];
__device__ __align__(16) __half g_w2l[KDIM * KDIM];
__device__ __align__(16) __half g_w3h[KDIM * MOUT];
__device__ __align__(16) __half g_w3l[KDIM * MOUT];
__device__ unsigned g_mask[NNODES * MASK_WORDS_PER_ROW];    // 8 MB
__device__ __align__(16) __half2 g_embh[NNODES * MOUT / 2]; // fp16 emb for GAT

// ---------------- mma / ldmatrix / cp.async helpers ----------------
__device__ __forceinline__ unsigned smem_u32(const void* p) {
    return (unsigned)__cvta_generic_to_shared(p);
}
__device__ __forceinline__ void cp16(unsigned dst, const void* src) {
    asm volatile("cp.async.ca.shared.global [%0], [%1], 16;" :: "r"(dst), "l"(src));
}
#define CP_COMMIT() asm volatile("cp.async.commit_group;")
#define CP_WAIT(N)  asm volatile("cp.async.wait_group %0;" :: "n"(N))

__device__ __forceinline__ void ldsm_x4(unsigned* r, unsigned addr) {
    asm volatile("ldmatrix.sync.aligned.m8n8.x4.shared.b16 {%0,%1,%2,%3}, [%4];"
                 : "=r"(r[0]), "=r"(r[1]), "=r"(r[2]), "=r"(r[3]) : "r"(addr));
}
__device__ __forceinline__ void ldsm_x4_t(unsigned* r, unsigned addr) {
    asm volatile("ldmatrix.sync.aligned.m8n8.x4.trans.shared.b16 {%0,%1,%2,%3}, [%4];"
                 : "=r"(r[0]), "=r"(r[1]), "=r"(r[2]), "=r"(r[3]) : "r"(addr));
}
__device__ __forceinline__ void mma16816(float* c, const unsigned* a,
                                         unsigned b0, unsigned b1) {
    asm volatile(
        "mma.sync.aligned.m16n8k16.row.col.f32.f16.f16.f32 "
        "{%0,%1,%2,%3}, {%4,%5,%6,%7}, {%8,%9}, {%0,%1,%2,%3};"
        : "+f"(c[0]), "+f"(c[1]), "+f"(c[2]), "+f"(c[3])
        : "r"(a[0]), "r"(a[1]), "r"(a[2]), "r"(a[3]), "r"(b0), "r"(b1));
}

// ---------------- split prep kernels ----------------
__device__ __forceinline__ void split1(float v, __half& hh, __half& hl) {
    hh = __float2half_rn(v);
    hl = __float2half_rn(v - __half2float(hh));
}
__global__ void split_x_kernel(const float* __restrict__ x) {
    int i = blockIdx.x * blockDim.x + threadIdx.x;   // over N*K = 2M, grid 8192x256
    float v = x[i];
    split1(v, g_xh[i], g_xl[i]);
}
__global__ void split_w1_kernel(const float* __restrict__ W) {
    int i = blockIdx.x * blockDim.x + threadIdx.x;   // 65536
    split1(W[i], g_w1h[i], g_w1l[i]);
}
__global__ void split_w2_kernel(const float* __restrict__ W) {
    int i = blockIdx.x * blockDim.x + threadIdx.x;
    split1(W[i], g_w2h[i], g_w2l[i]);
}
__global__ void split_w3_kernel(const float* __restrict__ W) {
    int i = blockIdx.x * blockDim.x + threadIdx.x;   // 32768
    split1(W[i], g_w3h[i], g_w3l[i]);
}

// ====== tensor-core GEMM + bias + LayerNorm (+tanh), 3-term fp16 split ======
// C = Xh@Wh + Xh@Wl + Xl@Wh  (error ~2^-22 per product, fp32 accumulate).
// 256 threads = 8 warps; CTA tile 32 rows x M. Warp w: row group (w&1)*16,
// col group (w>>1)*(M/4). mma.sync m16n8k16; A ldmatrix.x4, B ldmatrix.x4.trans.
// MODE 0: write tanh(LN(.)) as hi/lo fp16 (next layer). MODE 1: fp32 emb + fp16 copy.
template <int M, bool DO_TANH, int MODE>
__device__ __forceinline__
void gemm_body(const __half* __restrict__ Xh_g, const __half* __restrict__ Xl_g,
               const __half* __restrict__ Wh_g, const __half* __restrict__ Wl_g,
               const float* __restrict__ bias, const float* __restrict__ gam,
               const float* __restrict__ bet,
               __half* __restrict__ Hh, __half* __restrict__ Hl,
               float* __restrict__ emb)
{
    constexpr int K    = 256;
    constexpr int BK   = 32;
    constexpr int NT   = M / 32;            // ntiles per warp (8 or 4)
    constexpr int XS   = 40;                // X row stride (halfs): 80B, rotates banks
    constexpr int WS   = M + 8;             // W row stride (halfs): 528/272B
    constexpr int XBUF = 32 * XS * 2;       // bytes per X buffer
    constexpr int WBUF = BK * WS * 2;       // bytes per W buffer
    constexpr int OXH = 0;
    constexpr int OXL = OXH + 2 * XBUF;
    constexpr int OWH = OXL + 2 * XBUF;
    constexpr int OWL = OWH + 2 * WBUF;
    constexpr int OPAR = OWL + 2 * WBUF;
    constexpr int OSRED = OPAR + 3 * M * 4;

    extern __shared__ __align__(16) char smem_raw[];
    const unsigned sbase = smem_u32(smem_raw);

    float* bias_s = reinterpret_cast<float*>(smem_raw + OPAR);
    float* gam_s  = bias_s + M;
    float* bet_s  = bias_s + 2 * M;
    float* sred_s  = reinterpret_cast<float*>(smem_raw + OSRED);        // [4][32]
    float* sred_ss = sred_s + 128;                                      // [4][32]

    const int t    = threadIdx.x;
    const int lane = t & 31;
    const int w    = t >> 5;
    const int rg   = w & 1;
    const int cg   = w >> 1;                 // 0..3
    const int R    = rg * 16;
    const int C0   = cg * (M / 4);
    const int row0 = blockIdx.x * 32;
    const int g    = lane >> 2;
    const int tg   = lane & 3;

    // params to smem
    for (int i = t; i < M; i += 256) {
        bias_s[i] = bias[i];
        gam_s[i]  = gam[i];
        bet_s[i]  = bet[i];
    }

    // per-lane ldmatrix source coords
    const int arow = R + ((lane >> 3) & 1) * 8 + (lane & 7);
    const int acol = (lane >> 4) * 8;
    const int bk   = ((lane >> 3) & 1) * 8 + (lane & 7);
    const int bn   = (lane >> 4) * 8;
    const unsigned aH0 = sbase + OXH + (arow * XS + acol) * 2;
    const unsigned aL0 = sbase + OXL + (arow * XS + acol) * 2;
    const unsigned bH0 = sbase + OWH + (bk * WS + C0 + bn) * 2;
    const unsigned bL0 = sbase + OWL + (bk * WS + C0 + bn) * 2;

    // chunk loader
    auto load_chunk = [&](int c, int b) {
        const int k0 = c * BK;
        {   // X hi+lo: 2 arrays x 128 cp16 -> 1 per thread
            int arr = t >> 7, u = t & 127, r = u >> 2, seg = u & 3;
            const __half* src = (arr ? Xl_g : Xh_g) + (row0 + r) * K + k0 + seg * 8;
            unsigned dst = sbase + (arr ? OXL : OXH) + b * XBUF + (r * XS + seg * 8) * 2;
            cp16(dst, src);
        }
        constexpr int WSEG = M / 8;
        constexpr int ITER = (2 * 32 * WSEG) / 256;   // 8 (M=256) / 4 (M=128)
#pragma unroll
        for (int i = 0; i < ITER; i++) {
            int u = t + i * 256;
            int arr = u / (32 * WSEG);
            int v   = u % (32 * WSEG);
            int r   = v / WSEG;
            int seg = v % WSEG;
            const __half* src = (arr ? Wl_g : Wh_g) + (k0 + r) * M + seg * 8;
            unsigned dst = sbase + (arr ? OWL : OWH) + b * WBUF + (r * WS + seg * 8) * 2;
            cp16(dst, src);
        }
    };

    float c[NT][4];
#pragma unroll
    for (int n = 0; n < NT; n++)
#pragma unroll
        for (int j = 0; j < 4; j++) c[n][j] = 0.f;

    load_chunk(0, 0);
    CP_COMMIT();

    int buf = 0;
#pragma unroll 1
    for (int ch = 0; ch < K / BK; ch++) {
        if (ch + 1 < K / BK) {
            load_chunk(ch + 1, buf ^ 1);
            CP_COMMIT();
            CP_WAIT(1);
        } else {
            CP_WAIT(0);
        }
        __syncthreads();

#pragma unroll
        for (int ks = 0; ks < BK; ks += 16) {
            unsigned ah[4], al[4];
            ldsm_x4(ah, aH0 + buf * XBUF + ks * 2);
            ldsm_x4(al, aL0 + buf * XBUF + ks * 2);
#pragma unroll
            for (int p = 0; p < NT / 2; p++) {
                unsigned bh[4], bl[4];
                const unsigned boff = buf * WBUF + ks * WS * 2 + p * 32;
                ldsm_x4_t(bh, bH0 + boff);
                ldsm_x4_t(bl, bL0 + boff);
                mma16816(c[2 * p],     ah, bh[0], bh[1]);
                mma16816(c[2 * p],     ah, bl[0], bl[1]);
                mma16816(c[2 * p],     al, bh[0], bh[1]);
                mma16816(c[2 * p + 1], ah, bh[2], bh[3]);
                mma16816(c[2 * p + 1], ah, bl[2], bl[3]);
                mma16816(c[2 * p + 1], al, bh[2], bh[3]);
            }
        }
        __syncthreads();
        buf ^= 1;
    }

    // ---- epilogue: bias + LN partials (rows R+g, R+8+g) ----
    const int lr0 = R + g;          // local rows in [0,32)
    const int lr1 = R + 8 + g;
    float s0 = 0.f, ss0 = 0.f, s1 = 0.f, ss1 = 0.f;
#pragma unroll
    for (int n = 0; n < NT; n++) {
        const int col = C0 + n * 8 + 2 * tg;
        c[n][0] += bias_s[col];
        c[n][1] += bias_s[col + 1];
        c[n][2] += bias_s[col];
        c[n][3] += bias_s[col + 1];
        s0 += c[n][0] + c[n][1];  ss0 += c[n][0] * c[n][0] + c[n][1] * c[n][1];
        s1 += c[n][2] + c[n][3];  ss1 += c[n][2] * c[n][2] + c[n][3] * c[n][3];
    }
#pragma unroll
    for (int o = 1; o <= 2; o <<= 1) {
        s0  += __shfl_xor_sync(0xffffffffu, s0, o);
        ss0 += __shfl_xor_sync(0xffffffffu, ss0, o);
        s1  += __shfl_xor_sync(0xffffffffu, s1, o);
        ss1 += __shfl_xor_sync(0xffffffffu, ss1, o);
    }
    if (tg == 0) {
        sred_s [cg * 32 + lr0] = s0;  sred_ss[cg * 32 + lr0] = ss0;
        sred_s [cg * 32 + lr1] = s1;  sred_ss[cg * 32 + lr1] = ss1;
    }
    __syncthreads();

    float S0 = 0.f, SS0 = 0.f, S1 = 0.f, SS1 = 0.f;
#pragma unroll
    for (int q = 0; q < 4; q++) {
        S0 += sred_s[q * 32 + lr0];  SS0 += sred_ss[q * 32 + lr0];
        S1 += sred_s[q * 32 + lr1];  SS1 += sred_ss[q * 32 + lr1];
    }
    const float mu0 = S0 * (1.0f / M), rs0 = rsqrtf(SS0 * (1.0f / M) - mu0 * mu0 + EPSV);
    const float mu1 = S1 * (1.0f / M), rs1 = rsqrtf(SS1 * (1.0f / M) - mu1 * mu1 + EPSV);
    const int gr0 = row0 + lr0, gr1 = row0 + lr1;

#pragma unroll
    for (int n = 0; n < NT; n++) {
        const int col = C0 + n * 8 + 2 * tg;
        const float ga0 = gam_s[col], ga1 = gam_s[col + 1];
        const float be0 = bet_s[col], be1 = bet_s[col + 1];
        float o00 = (c[n][0] - mu0) * rs0 * ga0 + be0;
        float o01 = (c[n][1] - mu0) * rs0 * ga1 + be1;
        float o10 = (c[n][2] - mu1) * rs1 * ga0 + be0;
        float o11 = (c[n][3] - mu1) * rs1 * ga1 + be1;
        if (DO_TANH) { o00 = tanhf(o00); o01 = tanhf(o01); o10 = tanhf(o10); o11 = tanhf(o11); }

        if (MODE == 0) {
            __half h00, l00, h01, l01, h10, l10, h11, l11;
            split1(o00, h00, l00); split1(o01, h01, l01);
            split1(o10, h10, l10); split1(o11, h11, l11);
            *reinterpret_cast<__half2*>(&Hh[gr0 * M + col]) = __halves2half2(h00, h01);
            *reinterpret_cast<__half2*>(&Hl[gr0 * M + col]) = __halves2half2(l00, l01);
            *reinterpret_cast<__half2*>(&Hh[gr1 * M + col]) = __halves2half2(h10, h11);
            *reinterpret_cast<__half2*>(&Hl[gr1 * M + col]) = __halves2half2(l10, l11);
        } else {
            *reinterpret_cast<float2*>(&emb[gr0 * M + col]) = make_float2(o00, o01);
            *reinterpret_cast<float2*>(&emb[gr1 * M + col]) = make_float2(o10, o11);
            g_embh[(gr0 * M + col) / 2] = __floats2half2_rn(o00, o01);
            g_embh[(gr1 * M + col) / 2] = __floats2half2_rn(o10, o11);
        }
    }
}

// smem sizes (mirror of gemm_body layout)
#define SMEM_SZ_256 81920
#define SMEM_SZ_128 47616

__global__ __launch_bounds__(256)
void gemm_l1(const float* __restrict__ b, const float* __restrict__ g,
             const float* __restrict__ be)
{
    gemm_body<256, true, 0>(g_xh, g_xl, g_w1h, g_w1l, b, g, be, g_h1h, g_h1l, nullptr);
}
__global__ __launch_bounds__(256)
void gemm_l2(const float* __restrict__ b, const float* __restrict__ g,
             const float* __restrict__ be)
{
    gemm_body<256, true, 0>(g_h1h, g_h1l, g_w2h, g_w2l, b, g, be, g_h2h, g_h2l, nullptr);
}
__global__ __launch_bounds__(256)
void gemm_l3(const float* __restrict__ b, const float* __restrict__ g,
             const float* __restrict__ be, float* __restrict__ emb)
{
    gemm_body<128, false, 1>(g_h2h, g_h2l, g_w3h, g_w3l, b, g, be, nullptr, nullptr, emb);
}

// ---------------- adjacency bitmask ----------------
__global__ void zero_mask_kernel() {
    int i = blockIdx.x * blockDim.x + threadIdx.x;
    reinterpret_cast<uint4*>(g_mask)[i] = make_uint4(0u, 0u, 0u, 0u);
}
__global__ void set_edges_kernel(const int* __restrict__ ei, int E) {
    int e = blockIdx.x * blockDim.x + threadIdx.x;
    if (e >= E) return;
    int s = ei[e] - 1;
    int d = ei[E + e] - 1;
    atomicOr(&g_mask[(unsigned)(s * NNODES + d) >> 5], 1u << (d & 31));
    atomicOr(&g_mask[(unsigned)(d * NNODES + s) >> 5], 1u << (s & 31));
}

// ---------------- sparse GAT row kernel (single-pass, fp16 neighbors) ----------------
__global__ __launch_bounds__(128)
void gat_row_kernel(const float* __restrict__ emb, float* __restrict__ xgat)
{
    const int i    = blockIdx.x;
    const int t    = threadIdx.x;
    const int lane = t & 31;
    const int wid  = t >> 5;

    __shared__ __align__(16) float ei_s[MOUT];
    __shared__ __align__(16) float wout[4][MOUT];
    __shared__ __align__(16) int   nbr[MAX_DEG];
    __shared__ float wden[4];
    __shared__ int   cnt;

    ei_s[t] = emb[i * MOUT + t];
    if (t == 0) cnt = 0;
    __syncthreads();

    const unsigned* row = &g_mask[i * MASK_WORDS_PER_ROW];
#pragma unroll
    for (int w = t; w < MASK_WORDS_PER_ROW; w += 128) {
        unsigned m = row[w];
        while (m) {
            int b = __ffs(m) - 1;
            m &= m - 1;
            int p = atomicAdd(&cnt, 1);
            if (p < MAX_DEG) nbr[p] = w * 32 + b;
        }
    }
    __syncthreads();
    const int deg = cnt < MAX_DEG ? cnt : MAX_DEG;

    const float4 ei4 = *reinterpret_cast<const float4*>(&ei_s[lane * 4]);
    float4 oac = make_float4(0.f, 0.f, 0.f, 0.f);
    float  dsum = 0.f;

    for (int n = wid; n < deg; n += 4) {
        const __half2* hp = &g_embh[nbr[n] * (MOUT / 2) + lane * 2];
        const float2 f0 = __half22float2(hp[0]);
        const float2 f1 = __half22float2(hp[1]);
        float d = f0.x * ei4.x + f0.y * ei4.y + f1.x * ei4.z + f1.y * ei4.w;
#pragma unroll
        for (int o = 16; o > 0; o >>= 1) d += __shfl_xor_sync(0xffffffffu, d, o);
        const float s = expf(d);
        dsum  += s;
        oac.x += s * f0.x;
        oac.y += s * f0.y;
        oac.z += s * f1.x;
        oac.w += s * f1.y;
    }
    *reinterpret_cast<float4*>(&wout[wid][lane * 4]) = oac;
    if (lane == 0) wden[wid] = dsum;
    __syncthreads();

    const float den  = wden[0] + wden[1] + wden[2] + wden[3];
    const float invd = den > 0.f ? 1.0f / den : 0.0f;
    const float tot  = wout[0][t] + wout[1][t] + wout[2][t] + wout[3][t];
    xgat[i * MOUT + t] = tot * invd;
}

// ---------------- launch ----------------
extern "C" void kernel_launch(void* const* d_in, const int* in_sizes, int n_in,
                              void* d_out, int out_size)
{
    const float* x   = (const float*)d_in[0];
    const int*   ei  = (const int*)d_in[1];
    const float* w1  = (const float*)d_in[2];
    const float* b1  = (const float*)d_in[3];
    const float* g1  = (const float*)d_in[4];
    const float* be1 = (const float*)d_in[5];
    const float* w2  = (const float*)d_in[6];
    const float* b2  = (const float*)d_in[7];
    const float* g2  = (const float*)d_in[8];
    const float* be2 = (const float*)d_in[9];
    const float* w3  = (const float*)d_in[10];
    const float* b3  = (const float*)d_in[11];
    const float* g3  = (const float*)d_in[12];
    const float* be3 = (const float*)d_in[13];

    float* out  = (float*)d_out;
    float* emb  = out;                     // [N, 128]
    float* xgat = out + NNODES * MOUT;     // [N, 128]

    const int E = in_sizes[1] / 2;

    // raise dynamic smem limits (idempotent; not a stream op, capture-safe)
    cudaFuncSetAttribute(gemm_l1, cudaFuncAttributeMaxDynamicSharedMemorySize, SMEM_SZ_256);
    cudaFuncSetAttribute(gemm_l2, cudaFuncAttributeMaxDynamicSharedMemorySize, SMEM_SZ_256);
    cudaFuncSetAttribute(gemm_l3, cudaFuncAttributeMaxDynamicSharedMemorySize, SMEM_SZ_128);

    // prep: adjacency bitmask + fp16 hi/lo splits
    zero_mask_kernel<<<2048, 256>>>();
    set_edges_kernel<<<(E + 255) / 256, 256>>>(ei, E);
    split_x_kernel<<<8192, 256>>>(x);
    split_w1_kernel<<<256, 256>>>(w1);
    split_w2_kernel<<<256, 256>>>(w2);
    split_w3_kernel<<<128, 256>>>(w3);

    // encoder (tensor-core, 3-term split)
    gemm_l1<<<NNODES / 32, 256, SMEM_SZ_256>>>(b1, g1, be1);
    gemm_l2<<<NNODES / 32, 256, SMEM_SZ_256>>>(b2, g2, be2);
    gemm_l3<<<NNODES / 32, 256, SMEM_SZ_128>>>(b3, g3, be3, emb);

    // sparse GAT (fused single pass, fp16 neighbor reads)
    gat_row_kernel<<<NNODES, 128>>>(emb, xgat);
}

// round 16
// speedup vs baseline: 1.7181x; 1.1081x over previous
#include <cuda_runtime.h>
#include <cuda_fp16.h>
#include <cstdint>

#define NNODES 8192
#define KDIM   256
#define MOUT   128
#define EPSV   1e-5f
#define MASK_WORDS_PER_ROW (NNODES / 32)   // 256
#define MAX_DEG 2048

// ---------------- scratch (no cudaMalloc allowed) ----------------
__device__ __align__(16) __half g_xh [NNODES * KDIM];   // hi/lo fp16 splits
__device__ __align__(16) __half g_xl [NNODES * KDIM];
__device__ __align__(16) __half g_h1h[NNODES * KDIM];
__device__ __align__(16) __half g_h1l[NNODES * KDIM];
__device__ __align__(16) __half g_h2h[NNODES * KDIM];
__device__ __align__(16) __half g_h2l[NNODES * KDIM];
__device__ __align__(16) __half g_w1h[KDIM * KDIM];
__device__ __align__(16) __half g_w1l[KDIM * KDIM];
__device__ __align__(16) __half g_w2h[KDIM * KDIM];
__device__ __align__(16) __half g_w2l[KDIM * KDIM];
__device__ __align__(16) __half g_w3h[KDIM * MOUT];
__device__ __align__(16) __half g_w3l[KDIM * MOUT];
__device__ unsigned g_mask[NNODES * MASK_WORDS_PER_ROW];    // 8 MB
__device__ __align__(16) __half2 g_embh[NNODES * MOUT / 2]; // fp16 emb for GAT

// ---------------- mma / ldmatrix / cp.async helpers ----------------
__device__ __forceinline__ unsigned smem_u32(const void* p) {
    return (unsigned)__cvta_generic_to_shared(p);
}
__device__ __forceinline__ void cp16(unsigned dst, const void* src) {
    asm volatile("cp.async.ca.shared.global [%0], [%1], 16;" :: "r"(dst), "l"(src));
}
#define CP_COMMIT() asm volatile("cp.async.commit_group;")
#define CP_WAIT(N)  asm volatile("cp.async.wait_group %0;" :: "n"(N))

__device__ __forceinline__ void ldsm_x4(unsigned* r, unsigned addr) {
    asm volatile("ldmatrix.sync.aligned.m8n8.x4.shared.b16 {%0,%1,%2,%3}, [%4];"
                 : "=r"(r[0]), "=r"(r[1]), "=r"(r[2]), "=r"(r[3]) : "r"(addr));
}
__device__ __forceinline__ void ldsm_x4_t(unsigned* r, unsigned addr) {
    asm volatile("ldmatrix.sync.aligned.m8n8.x4.trans.shared.b16 {%0,%1,%2,%3}, [%4];"
                 : "=r"(r[0]), "=r"(r[1]), "=r"(r[2]), "=r"(r[3]) : "r"(addr));
}
__device__ __forceinline__ void mma16816(float* c, const unsigned* a,
                                         unsigned b0, unsigned b1) {
    asm volatile(
        "mma.sync.aligned.m16n8k16.row.col.f32.f16.f16.f32 "
        "{%0,%1,%2,%3}, {%4,%5,%6,%7}, {%8,%9}, {%0,%1,%2,%3};"
        : "+f"(c[0]), "+f"(c[1]), "+f"(c[2]), "+f"(c[3])
        : "r"(a[0]), "r"(a[1]), "r"(a[2]), "r"(a[3]), "r"(b0), "r"(b1));
}

// ---------------- fused prep kernel ----------------
// Block ranges: [0,2048)   zero g_mask (uint4)
//               [2048,4096) split x (float4 -> 4 hi/lo halfs)
//               [4096,4160) split w1, [4160,4224) split w2, [4224,4256) split w3
__device__ __forceinline__ void split1(float v, __half& hh, __half& hl) {
    hh = __float2half_rn(v);
    hl = __float2half_rn(v - __half2float(hh));
}
__device__ __forceinline__ void split4(const float4 v, __half* hh, __half* hl) {
    split1(v.x, hh[0], hl[0]);
    split1(v.y, hh[1], hl[1]);
    split1(v.z, hh[2], hl[2]);
    split1(v.w, hh[3], hl[3]);
}
__global__ void prep_kernel(const float* __restrict__ x,
                            const float* __restrict__ w1,
                            const float* __restrict__ w2,
                            const float* __restrict__ w3)
{
    const int b = blockIdx.x;
    const int t = threadIdx.x;
    if (b < 2048) {
        reinterpret_cast<uint4*>(g_mask)[b * 256 + t] = make_uint4(0u, 0u, 0u, 0u);
    } else if (b < 4096) {
        int i = (b - 2048) * 256 + t;                 // over 524288 float4
        float4 v = reinterpret_cast<const float4*>(x)[i];
        __half hh[4], hl[4];
        split4(v, hh, hl);
        *reinterpret_cast<uint2*>(&g_xh[i * 4]) = *reinterpret_cast<uint2*>(hh);
        *reinterpret_cast<uint2*>(&g_xl[i * 4]) = *reinterpret_cast<uint2*>(hl);
    } else if (b < 4160) {
        int i = (b - 4096) * 256 + t;                 // 16384 float4
        float4 v = reinterpret_cast<const float4*>(w1)[i];
        __half hh[4], hl[4];
        split4(v, hh, hl);
        *reinterpret_cast<uint2*>(&g_w1h[i * 4]) = *reinterpret_cast<uint2*>(hh);
        *reinterpret_cast<uint2*>(&g_w1l[i * 4]) = *reinterpret_cast<uint2*>(hl);
    } else if (b < 4224) {
        int i = (b - 4160) * 256 + t;
        float4 v = reinterpret_cast<const float4*>(w2)[i];
        __half hh[4], hl[4];
        split4(v, hh, hl);
        *reinterpret_cast<uint2*>(&g_w2h[i * 4]) = *reinterpret_cast<uint2*>(hh);
        *reinterpret_cast<uint2*>(&g_w2l[i * 4]) = *reinterpret_cast<uint2*>(hl);
    } else {
        int i = (b - 4224) * 256 + t;                 // 8192 float4
        float4 v = reinterpret_cast<const float4*>(w3)[i];
        __half hh[4], hl[4];
        split4(v, hh, hl);
        *reinterpret_cast<uint2*>(&g_w3h[i * 4]) = *reinterpret_cast<uint2*>(hh);
        *reinterpret_cast<uint2*>(&g_w3l[i * 4]) = *reinterpret_cast<uint2*>(hl);
    }
}

__global__ void set_edges_kernel(const int* __restrict__ ei, int E) {
    int e = blockIdx.x * blockDim.x + threadIdx.x;
    if (e >= E) return;
    int s = ei[e] - 1;
    int d = ei[E + e] - 1;
    atomicOr(&g_mask[(unsigned)(s * NNODES + d) >> 5], 1u << (d & 31));
    atomicOr(&g_mask[(unsigned)(d * NNODES + s) >> 5], 1u << (s & 31));
}

// ====== tensor-core GEMM + bias + LayerNorm (+tanh), 3-term fp16 split ======
// C = Xh@Wh + Xh@Wl + Xl@Wh  (error ~2^-22 per product, fp32 accumulate).
// 256 threads = 8 warps; CTA tile 32 rows x M. Warp w: row group (w&1)*16,
// col group (w>>1)*(M/4). mma.sync m16n8k16; A ldmatrix.x4, B ldmatrix.x4.trans.
// MODE 0: write tanh(LN(.)) as hi/lo fp16. MODE 1: fp32 emb + fp16 copy.
template <int M, bool DO_TANH, int MODE>
__device__ __forceinline__
void gemm_body(const __half* __restrict__ Xh_g, const __half* __restrict__ Xl_g,
               const __half* __restrict__ Wh_g, const __half* __restrict__ Wl_g,
               const float* __restrict__ bias, const float* __restrict__ gam,
               const float* __restrict__ bet,
               __half* __restrict__ Hh, __half* __restrict__ Hl,
               float* __restrict__ emb)
{
    constexpr int K    = 256;
    constexpr int BK   = 32;
    constexpr int NT   = M / 32;
    constexpr int XS   = 40;
    constexpr int WS   = M + 8;
    constexpr int XBUF = 32 * XS * 2;
    constexpr int WBUF = BK * WS * 2;
    constexpr int OXH = 0;
    constexpr int OXL = OXH + 2 * XBUF;
    constexpr int OWH = OXL + 2 * XBUF;
    constexpr int OWL = OWH + 2 * WBUF;
    constexpr int OPAR = OWL + 2 * WBUF;
    constexpr int OSRED = OPAR + 3 * M * 4;

    extern __shared__ __align__(16) char smem_raw[];
    const unsigned sbase = smem_u32(smem_raw);

    float* bias_s = reinterpret_cast<float*>(smem_raw + OPAR);
    float* gam_s  = bias_s + M;
    float* bet_s  = bias_s + 2 * M;
    float* sred_s  = reinterpret_cast<float*>(smem_raw + OSRED);
    float* sred_ss = sred_s + 128;

    const int t    = threadIdx.x;
    const int lane = t & 31;
    const int w    = t >> 5;
    const int rg   = w & 1;
    const int cg   = w >> 1;
    const int R    = rg * 16;
    const int C0   = cg * (M / 4);
    const int row0 = blockIdx.x * 32;
    const int g    = lane >> 2;
    const int tg   = lane & 3;

    for (int i = t; i < M; i += 256) {
        bias_s[i] = bias[i];
        gam_s[i]  = gam[i];
        bet_s[i]  = bet[i];
    }

    const int arow = R + ((lane >> 3) & 1) * 8 + (lane & 7);
    const int acol = (lane >> 4) * 8;
    const int bk   = ((lane >> 3) & 1) * 8 + (lane & 7);
    const int bn   = (lane >> 4) * 8;
    const unsigned aH0 = sbase + OXH + (arow * XS + acol) * 2;
    const unsigned aL0 = sbase + OXL + (arow * XS + acol) * 2;
    const unsigned bH0 = sbase + OWH + (bk * WS + C0 + bn) * 2;
    const unsigned bL0 = sbase + OWL + (bk * WS + C0 + bn) * 2;

    auto load_chunk = [&](int c, int b) {
        const int k0 = c * BK;
        {
            int arr = t >> 7, u = t & 127, r = u >> 2, seg = u & 3;
            const __half* src = (arr ? Xl_g : Xh_g) + (row0 + r) * K + k0 + seg * 8;
            unsigned dst = sbase + (arr ? OXL : OXH) + b * XBUF + (r * XS + seg * 8) * 2;
            cp16(dst, src);
        }
        constexpr int WSEG = M / 8;
        constexpr int ITER = (2 * 32 * WSEG) / 256;
#pragma unroll
        for (int i = 0; i < ITER; i++) {
            int u = t + i * 256;
            int arr = u / (32 * WSEG);
            int v   = u % (32 * WSEG);
            int r   = v / WSEG;
            int seg = v % WSEG;
            const __half* src = (arr ? Wl_g : Wh_g) + (k0 + r) * M + seg * 8;
            unsigned dst = sbase + (arr ? OWL : OWH) + b * WBUF + (r * WS + seg * 8) * 2;
            cp16(dst, src);
        }
    };

    float c[NT][4];
#pragma unroll
    for (int n = 0; n < NT; n++)
#pragma unroll
        for (int j = 0; j < 4; j++) c[n][j] = 0.f;

    load_chunk(0, 0);
    CP_COMMIT();

    int buf = 0;
#pragma unroll 1
    for (int ch = 0; ch < K / BK; ch++) {
        if (ch + 1 < K / BK) {
            load_chunk(ch + 1, buf ^ 1);
            CP_COMMIT();
            CP_WAIT(1);
        } else {
            CP_WAIT(0);
        }
        __syncthreads();

#pragma unroll
        for (int ks = 0; ks < BK; ks += 16) {
            unsigned ah[4], al[4];
            ldsm_x4(ah, aH0 + buf * XBUF + ks * 2);
            ldsm_x4(al, aL0 + buf * XBUF + ks * 2);
#pragma unroll
            for (int p = 0; p < NT / 2; p++) {
                unsigned bh[4], bl[4];
                const unsigned boff = buf * WBUF + ks * WS * 2 + p * 32;
                ldsm_x4_t(bh, bH0 + boff);
                ldsm_x4_t(bl, bL0 + boff);
                mma16816(c[2 * p],     ah, bh[0], bh[1]);
                mma16816(c[2 * p],     ah, bl[0], bl[1]);
                mma16816(c[2 * p],     al, bh[0], bh[1]);
                mma16816(c[2 * p + 1], ah, bh[2], bh[3]);
                mma16816(c[2 * p + 1], ah, bl[2], bl[3]);
                mma16816(c[2 * p + 1], al, bh[2], bh[3]);
            }
        }
        __syncthreads();
        buf ^= 1;
    }

    // ---- epilogue: bias + LN partials (rows R+g, R+8+g) ----
    const int lr0 = R + g;
    const int lr1 = R + 8 + g;
    float s0 = 0.f, ss0 = 0.f, s1 = 0.f, ss1 = 0.f;
#pragma unroll
    for (int n = 0; n < NT; n++) {
        const int col = C0 + n * 8 + 2 * tg;
        c[n][0] += bias_s[col];
        c[n][1] += bias_s[col + 1];
        c[n][2] += bias_s[col];
        c[n][3] += bias_s[col + 1];
        s0 += c[n][0] + c[n][1];  ss0 += c[n][0] * c[n][0] + c[n][1] * c[n][1];
        s1 += c[n][2] + c[n][3];  ss1 += c[n][2] * c[n][2] + c[n][3] * c[n][3];
    }
#pragma unroll
    for (int o = 1; o <= 2; o <<= 1) {
        s0  += __shfl_xor_sync(0xffffffffu, s0, o);
        ss0 += __shfl_xor_sync(0xffffffffu, ss0, o);
        s1  += __shfl_xor_sync(0xffffffffu, s1, o);
        ss1 += __shfl_xor_sync(0xffffffffu, ss1, o);
    }
    if (tg == 0) {
        sred_s [cg * 32 + lr0] = s0;  sred_ss[cg * 32 + lr0] = ss0;
        sred_s [cg * 32 + lr1] = s1;  sred_ss[cg * 32 + lr1] = ss1;
    }
    __syncthreads();

    float S0 = 0.f, SS0 = 0.f, S1 = 0.f, SS1 = 0.f;
#pragma unroll
    for (int q = 0; q < 4; q++) {
        S0 += sred_s[q * 32 + lr0];  SS0 += sred_ss[q * 32 + lr0];
        S1 += sred_s[q * 32 + lr1];  SS1 += sred_ss[q * 32 + lr1];
    }
    const float mu0 = S0 * (1.0f / M), rs0 = rsqrtf(SS0 * (1.0f / M) - mu0 * mu0 + EPSV);
    const float mu1 = S1 * (1.0f / M), rs1 = rsqrtf(SS1 * (1.0f / M) - mu1 * mu1 + EPSV);
    const int gr0 = row0 + lr0, gr1 = row0 + lr1;

#pragma unroll
    for (int n = 0; n < NT; n++) {
        const int col = C0 + n * 8 + 2 * tg;
        const float ga0 = gam_s[col], ga1 = gam_s[col + 1];
        const float be0 = bet_s[col], be1 = bet_s[col + 1];
        float o00 = (c[n][0] - mu0) * rs0 * ga0 + be0;
        float o01 = (c[n][1] - mu0) * rs0 * ga1 + be1;
        float o10 = (c[n][2] - mu1) * rs1 * ga0 + be0;
        float o11 = (c[n][3] - mu1) * rs1 * ga1 + be1;
        if (DO_TANH) { o00 = tanhf(o00); o01 = tanhf(o01); o10 = tanhf(o10); o11 = tanhf(o11); }

        if (MODE == 0) {
            __half h00, l00, h01, l01, h10, l10, h11, l11;
            split1(o00, h00, l00); split1(o01, h01, l01);
            split1(o10, h10, l10); split1(o11, h11, l11);
            *reinterpret_cast<__half2*>(&Hh[gr0 * M + col]) = __halves2half2(h00, h01);
            *reinterpret_cast<__half2*>(&Hl[gr0 * M + col]) = __halves2half2(l00, l01);
            *reinterpret_cast<__half2*>(&Hh[gr1 * M + col]) = __halves2half2(h10, h11);
            *reinterpret_cast<__half2*>(&Hl[gr1 * M + col]) = __halves2half2(l10, l11);
        } else {
            *reinterpret_cast<float2*>(&emb[gr0 * M + col]) = make_float2(o00, o01);
            *reinterpret_cast<float2*>(&emb[gr1 * M + col]) = make_float2(o10, o11);
            g_embh[(gr0 * M + col) / 2] = __floats2half2_rn(o00, o01);
            g_embh[(gr1 * M + col) / 2] = __floats2half2_rn(o10, o11);
        }
    }
}

#define SMEM_SZ_256 81920
#define SMEM_SZ_128 47616

__global__ __launch_bounds__(256)
void gemm_l1(const float* __restrict__ b, const float* __restrict__ g,
             const float* __restrict__ be)
{
    gemm_body<256, true, 0>(g_xh, g_xl, g_w1h, g_w1l, b, g, be, g_h1h, g_h1l, nullptr);
}
__global__ __launch_bounds__(256)
void gemm_l2(const float* __restrict__ b, const float* __restrict__ g,
             const float* __restrict__ be)
{
    gemm_body<256, true, 0>(g_h1h, g_h1l, g_w2h, g_w2l, b, g, be, g_h2h, g_h2l, nullptr);
}
__global__ __launch_bounds__(256)
void gemm_l3(const float* __restrict__ b, const float* __restrict__ g,
             const float* __restrict__ be, float* __restrict__ emb)
{
    gemm_body<128, false, 1>(g_h2h, g_h2l, g_w3h, g_w3l, b, g, be, nullptr, nullptr, emb);
}

// ---------------- sparse GAT row kernel (single-pass, fp16, 2-way ILP) ----------------
// One block per node i (128 threads = 4 warps). Each warp processes TWO
// neighbors per iteration (n, n+4) — two independent dot/shfl/exp chains in
// flight doubles MLP against the ~230cyc L2 latency (GAT is L2-bound).
__global__ __launch_bounds__(128)
void gat_row_kernel(const float* __restrict__ emb, float* __restrict__ xgat)
{
    const int i    = blockIdx.x;
    const int t    = threadIdx.x;
    const int lane = t & 31;
    const int wid  = t >> 5;

    __shared__ __align__(16) float ei_s[MOUT];
    __shared__ __align__(16) float wout[4][MOUT];
    __shared__ __align__(16) int   nbr[MAX_DEG];
    __shared__ float wden[4];
    __shared__ int   cnt;

    ei_s[t] = emb[i * MOUT + t];
    if (t == 0) cnt = 0;
    __syncthreads();

    const unsigned* row = &g_mask[i * MASK_WORDS_PER_ROW];
#pragma unroll
    for (int w = t; w < MASK_WORDS_PER_ROW; w += 128) {
        unsigned m = row[w];
        while (m) {
            int b = __ffs(m) - 1;
            m &= m - 1;
            int p = atomicAdd(&cnt, 1);
            if (p < MAX_DEG) nbr[p] = w * 32 + b;
        }
    }
    __syncthreads();
    const int deg = cnt < MAX_DEG ? cnt : MAX_DEG;

    const float4 ei4 = *reinterpret_cast<const float4*>(&ei_s[lane * 4]);
    float4 oac = make_float4(0.f, 0.f, 0.f, 0.f);
    float  dsum = 0.f;

    int n = wid;
    for (; n + 4 < deg; n += 8) {
        const __half2* hpA = &g_embh[nbr[n]     * (MOUT / 2) + lane * 2];
        const __half2* hpB = &g_embh[nbr[n + 4] * (MOUT / 2) + lane * 2];
        const float2 a0 = __half22float2(hpA[0]);
        const float2 a1 = __half22float2(hpA[1]);
        const float2 b0 = __half22float2(hpB[0]);
        const float2 b1 = __half22float2(hpB[1]);
        float dA = a0.x * ei4.x + a0.y * ei4.y + a1.x * ei4.z + a1.y * ei4.w;
        float dB = b0.x * ei4.x + b0.y * ei4.y + b1.x * ei4.z + b1.y * ei4.w;
#pragma unroll
        for (int o = 16; o > 0; o >>= 1) {
            dA += __shfl_xor_sync(0xffffffffu, dA, o);
            dB += __shfl_xor_sync(0xffffffffu, dB, o);
        }
        const float sA = expf(dA);
        const float sB = expf(dB);
        dsum  += sA + sB;
        oac.x += sA * a0.x + sB * b0.x;
        oac.y += sA * a0.y + sB * b0.y;
        oac.z += sA * a1.x + sB * b1.x;
        oac.w += sA * a1.y + sB * b1.y;
    }
    for (; n < deg; n += 4) {
        const __half2* hp = &g_embh[nbr[n] * (MOUT / 2) + lane * 2];
        const float2 f0 = __half22float2(hp[0]);
        const float2 f1 = __half22float2(hp[1]);
        float d = f0.x * ei4.x + f0.y * ei4.y + f1.x * ei4.z + f1.y * ei4.w;
#pragma unroll
        for (int o = 16; o > 0; o >>= 1) d += __shfl_xor_sync(0xffffffffu, d, o);
        const float s = expf(d);
        dsum  += s;
        oac.x += s * f0.x;
        oac.y += s * f0.y;
        oac.z += s * f1.x;
        oac.w += s * f1.y;
    }
    *reinterpret_cast<float4*>(&wout[wid][lane * 4]) = oac;
    if (lane == 0) wden[wid] = dsum;
    __syncthreads();

    const float den  = wden[0] + wden[1] + wden[2] + wden[3];
    const float invd = den > 0.f ? 1.0f / den : 0.0f;
    const float tot  = wout[0][t] + wout[1][t] + wout[2][t] + wout[3][t];
    xgat[i * MOUT + t] = tot * invd;
}

// ---------------- launch ----------------
extern "C" void kernel_launch(void* const* d_in, const int* in_sizes, int n_in,
                              void* d_out, int out_size)
{
    const float* x   = (const float*)d_in[0];
    const int*   ei  = (const int*)d_in[1];
    const float* w1  = (const float*)d_in[2];
    const float* b1  = (const float*)d_in[3];
    const float* g1  = (const float*)d_in[4];
    const float* be1 = (const float*)d_in[5];
    const float* w2  = (const float*)d_in[6];
    const float* b2  = (const float*)d_in[7];
    const float* g2  = (const float*)d_in[8];
    const float* be2 = (const float*)d_in[9];
    const float* w3  = (const float*)d_in[10];
    const float* b3  = (const float*)d_in[11];
    const float* g3  = (const float*)d_in[12];
    const float* be3 = (const float*)d_in[13];

    float* out  = (float*)d_out;
    float* emb  = out;                     // [N, 128]
    float* xgat = out + NNODES * MOUT;     // [N, 128]

    const int E = in_sizes[1] / 2;

    cudaFuncSetAttribute(gemm_l1, cudaFuncAttributeMaxDynamicSharedMemorySize, SMEM_SZ_256);
    cudaFuncSetAttribute(gemm_l2, cudaFuncAttributeMaxDynamicSharedMemorySize, SMEM_SZ_256);
    cudaFuncSetAttribute(gemm_l3, cudaFuncAttributeMaxDynamicSharedMemorySize, SMEM_SZ_128);

    // fused prep (mask zero + all hi/lo splits), then edge scatter
    prep_kernel<<<4256, 256>>>(x, w1, w2, w3);
    set_edges_kernel<<<(E + 255) / 256, 256>>>(ei, E);

    // encoder (tensor-core, 3-term split)
    gemm_l1<<<NNODES / 32, 256, SMEM_SZ_256>>>(b1, g1, be1);
    gemm_l2<<<NNODES / 32, 256, SMEM_SZ_256>>>(b2, g2, be2);
    gemm_l3<<<NNODES / 32, 256, SMEM_SZ_128>>>(b3, g3, be3, emb);

    // sparse GAT (fused single pass, fp16, 2-neighbor ILP)
    gat_row_kernel<<<NNODES, 128>>>(emb, xgat);
}